// round 16
// baseline (speedup 1.0000x reference)
#include <cuda_runtime.h>
#include <cuda_bf16.h>
#include <math.h>
#include <stddef.h>

// Problem constants
#define BB 2
#define SS 2048
#define DM 1024
#define NH 16
#define DK 64
#define BHX (BB * NH)   // 32

// ---------------------------------------------------------------------------
// Scratch (device globals; no allocation allowed)
// ---------------------------------------------------------------------------
__device__ float g_Q [(size_t)BB * SS * DM];
__device__ float g_Kp[(size_t)BB * SS * DK];
__device__ float g_Vp[(size_t)BB * SS * DK];
__device__ float g_AO[(size_t)BB * SS * DM];
__device__ float g_attn_scratch[(size_t)BB * NH * SS * SS];

// ---------------------------------------------------------------------------
// TF32 helpers (fragment layouts validated in R7)
// ---------------------------------------------------------------------------
__device__ __forceinline__ unsigned f2tf(float x) {
    unsigned r;
    asm("cvt.rna.tf32.f32 %0, %1;" : "=r"(r) : "f"(x));
    return r;
}

__device__ __forceinline__ unsigned u2tf(unsigned ub) {
    return f2tf(__uint_as_float(ub));
}

__device__ __forceinline__ void mma_tf32(float c[4], const unsigned a[4], const unsigned b[2]) {
    asm volatile(
        "mma.sync.aligned.m16n8k8.row.col.f32.tf32.tf32.f32 "
        "{%0,%1,%2,%3}, {%4,%5,%6,%7}, {%8,%9}, {%0,%1,%2,%3};"
        : "+f"(c[0]), "+f"(c[1]), "+f"(c[2]), "+f"(c[3])
        : "r"(a[0]), "r"(a[1]), "r"(a[2]), "r"(a[3]), "r"(b[0]), "r"(b[1]));
}

// ---------------------------------------------------------------------------
// cp.async helpers
// ---------------------------------------------------------------------------
__device__ __forceinline__ void cp_async16(const void* smem_ptr, const void* gmem_ptr) {
    unsigned sa = (unsigned)__cvta_generic_to_shared(smem_ptr);
    asm volatile("cp.async.cg.shared.global [%0], [%1], 16;" :: "r"(sa), "l"(gmem_ptr));
}
__device__ __forceinline__ void cp_commit() {
    asm volatile("cp.async.commit_group;");
}

// ---------------------------------------------------------------------------
// BF16 helpers (m16n8k16; validated in R13)
// ---------------------------------------------------------------------------
__device__ __forceinline__ void mma_bf16(float c[4], const unsigned a[4], const unsigned b[2]) {
    asm volatile(
        "mma.sync.aligned.m16n8k16.row.col.f32.bf16.bf16.f32 "
        "{%0,%1,%2,%3}, {%4,%5,%6,%7}, {%8,%9}, {%0,%1,%2,%3};"
        : "+f"(c[0]), "+f"(c[1]), "+f"(c[2]), "+f"(c[3])
        : "r"(a[0]), "r"(a[1]), "r"(a[2]), "r"(a[3]), "r"(b[0]), "r"(b[1]));
}

__device__ __forceinline__ void split2_bf16(float x, float y, unsigned& h, unsigned& l) {
    __nv_bfloat16 hx = __float2bfloat16_rn(x);
    __nv_bfloat16 hy = __float2bfloat16_rn(y);
    __nv_bfloat16 lx = __float2bfloat16_rn(x - __bfloat162float(hx));
    __nv_bfloat16 ly = __float2bfloat16_rn(y - __bfloat162float(hy));
    h = (unsigned)__bfloat16_as_ushort(hx) | ((unsigned)__bfloat16_as_ushort(hy) << 16);
    l = (unsigned)__bfloat16_as_ushort(lx) | ((unsigned)__bfloat16_as_ushort(ly) << 16);
}

// ---------------------------------------------------------------------------
// Fused K/V projection: grid.y = 0 -> K, 1 -> V.  SIMT fp32, N=64.
// One launch, 128 blocks (vs two serial 64-block launches).
// ---------------------------------------------------------------------------
__global__ void gemm_bias_kv_kernel(const float* __restrict__ Kin,
                                    const float* __restrict__ Vin,
                                    const float* __restrict__ w_k,
                                    const float* __restrict__ b_k,
                                    const float* __restrict__ w_v,
                                    const float* __restrict__ b_v,
                                    float* __restrict__ Kout,
                                    float* __restrict__ Vout) {
    const int which = blockIdx.y;
    const float* A    = which ? Vin  : Kin;
    const float* W    = which ? w_v  : w_k;
    const float* bias = which ? b_v  : b_k;
    float*       C    = which ? Vout : Kout;

    const int M = BB * SS;      // 4096
    const int K = DM;           // 1024
    const int N = DK;           // 64

    __shared__ float As[16][68];
    __shared__ float Ws[16][64];

    const int tid = threadIdx.x;
    const int tx = tid & 15;
    const int ty = tid >> 4;
    const int bm = blockIdx.x * 64;

    float acc[4][4] = {};

    for (int k0 = 0; k0 < K; k0 += 16) {
        #pragma unroll
        for (int i = tid; i < 64 * 16; i += 256) {
            int m = i >> 4, k = i & 15;
            As[k][m] = A[(size_t)(bm + m) * K + k0 + k];
        }
        #pragma unroll
        for (int i = tid; i < 16 * 64; i += 256) {
            int k = i >> 6, n = i & 63;
            Ws[k][n] = W[(size_t)(k0 + k) * N + n];
        }
        __syncthreads();

        #pragma unroll
        for (int k = 0; k < 16; k++) {
            float4 avv = *reinterpret_cast<const float4*>(&As[k][ty * 4]);
            float a[4] = {avv.x, avv.y, avv.z, avv.w};
            float4 bv = *reinterpret_cast<const float4*>(&Ws[k][tx * 4]);
            float b[4] = {bv.x, bv.y, bv.z, bv.w};
            #pragma unroll
            for (int i = 0; i < 4; i++)
                #pragma unroll
                for (int j = 0; j < 4; j++)
                    acc[i][j] = fmaf(a[i], b[j], acc[i][j]);
        }
        __syncthreads();
    }

    #pragma unroll
    for (int i = 0; i < 4; i++) {
        int m = bm + ty * 4 + i;
        #pragma unroll
        for (int j = 0; j < 4; j++) {
            int n = tx * 4 + j;
            C[(size_t)m * N + n] = acc[i][j] + bias[n];
        }
    }
}

// ---------------------------------------------------------------------------
// BF16-split ("bf16x3") tensor-core GEMM with bias (validated R13)
// ---------------------------------------------------------------------------
__global__ void gemm_bias_bf16x3_kernel(const float* __restrict__ A,
                                        const float* __restrict__ W,
                                        const float* __restrict__ bias,
                                        float* __restrict__ C,
                                        int M, int K, int N) {
    __shared__ unsigned Ah[128][13];
    __shared__ unsigned Al[128][13];
    __shared__ unsigned Wh[128][13];
    __shared__ unsigned Wl[128][13];

    const int tid = threadIdx.x;
    const int warp = tid >> 5;
    const int lane = tid & 31;
    const int wm = (warp >> 2) * 64;
    const int wn = (warp & 3) * 32;
    const int lr = lane >> 2;
    const int lc = lane & 3;
    const int bm = blockIdx.x * 128;
    const int bn = blockIdx.y * 128;

    float c[4][4][4] = {};

    for (int k0 = 0; k0 < K; k0 += 16) {
        {
            const int r = tid >> 1;
            const int cb = (tid & 1) * 8;
            const int pb = (tid & 1) * 4;
            const float* src = &A[(size_t)(bm + r) * K + k0 + cb];
            float4 v0 = *reinterpret_cast<const float4*>(src);
            float4 v1 = *reinterpret_cast<const float4*>(src + 4);
            unsigned h, l;
            split2_bf16(v0.x, v0.y, h, l); Ah[r][pb + 0] = h; Al[r][pb + 0] = l;
            split2_bf16(v0.z, v0.w, h, l); Ah[r][pb + 1] = h; Al[r][pb + 1] = l;
            split2_bf16(v1.x, v1.y, h, l); Ah[r][pb + 2] = h; Al[r][pb + 2] = l;
            split2_bf16(v1.z, v1.w, h, l); Ah[r][pb + 3] = h; Al[r][pb + 3] = l;
        }
        {
            const int kk2 = warp * 2;
            const int nb = lane * 4;
            const float* src0 = &W[(size_t)(k0 + kk2    ) * N + bn + nb];
            const float* src1 = &W[(size_t)(k0 + kk2 + 1) * N + bn + nb];
            float4 r0 = *reinterpret_cast<const float4*>(src0);
            float4 r1 = *reinterpret_cast<const float4*>(src1);
            unsigned h, l;
            split2_bf16(r0.x, r1.x, h, l); Wh[nb + 0][warp] = h; Wl[nb + 0][warp] = l;
            split2_bf16(r0.y, r1.y, h, l); Wh[nb + 1][warp] = h; Wl[nb + 1][warp] = l;
            split2_bf16(r0.z, r1.z, h, l); Wh[nb + 2][warp] = h; Wl[nb + 2][warp] = l;
            split2_bf16(r0.w, r1.w, h, l); Wh[nb + 3][warp] = h; Wl[nb + 3][warp] = l;
        }
        __syncthreads();

        unsigned ah[4][4], al[4][4], bh[4][2], bl[4][2];
        #pragma unroll
        for (int mt = 0; mt < 4; mt++) {
            int r0 = wm + mt * 16 + lr;
            ah[mt][0] = Ah[r0    ][lc];
            ah[mt][1] = Ah[r0 + 8][lc];
            ah[mt][2] = Ah[r0    ][lc + 4];
            ah[mt][3] = Ah[r0 + 8][lc + 4];
            al[mt][0] = Al[r0    ][lc];
            al[mt][1] = Al[r0 + 8][lc];
            al[mt][2] = Al[r0    ][lc + 4];
            al[mt][3] = Al[r0 + 8][lc + 4];
        }
        #pragma unroll
        for (int nt = 0; nt < 4; nt++) {
            int n0 = wn + nt * 8 + lr;
            bh[nt][0] = Wh[n0][lc];
            bh[nt][1] = Wh[n0][lc + 4];
            bl[nt][0] = Wl[n0][lc];
            bl[nt][1] = Wl[n0][lc + 4];
        }
        #pragma unroll
        for (int mt = 0; mt < 4; mt++)
            #pragma unroll
            for (int nt = 0; nt < 4; nt++) {
                mma_bf16(c[mt][nt], al[mt], bh[nt]);
                mma_bf16(c[mt][nt], ah[mt], bl[nt]);
                mma_bf16(c[mt][nt], ah[mt], bh[nt]);
            }
        __syncthreads();
    }

    #pragma unroll
    for (int mt = 0; mt < 4; mt++) {
        #pragma unroll
        for (int half = 0; half < 2; half++) {
            int m = bm + wm + mt * 16 + lr + half * 8;
            #pragma unroll
            for (int nt = 0; nt < 4; nt++) {
                int n = bn + wn + nt * 8 + lc * 2;
                float2 bv = *reinterpret_cast<const float2*>(&bias[n]);
                float2 v;
                v.x = c[mt][nt][half * 2 + 0] + bv.x;
                v.y = c[mt][nt][half * 2 + 1] + bv.y;
                *reinterpret_cast<float2*>(&C[(size_t)m * N + n]) = v;
            }
        }
    }
}

// ---------------------------------------------------------------------------
// Scores via TF32 MMA.  NEW: coalesced epilogue — fragments scatter to smem
// (conflict-free, stride 136), then fully-coalesced float4 row stores.
// Qs/Ks smem is reused for the epilogue staging (union via raw buffer).
// ---------------------------------------------------------------------------
__global__ void scores_tc_kernel(float* __restrict__ attn) {
    const int bh = blockIdx.z;
    const int b = bh >> 4;
    const int h = bh & 15;
    const int bm = blockIdx.x * 128;
    const int bn = blockIdx.y * 128;

    // Union: load phase uses Qs/Ks [128][36] each; epilogue uses epi[64][136].
    __shared__ __align__(16) unsigned sraw[2 * 128 * 36];   // 36.9 KB
    unsigned (*Qs)[36] = reinterpret_cast<unsigned(*)[36]>(sraw);
    unsigned (*Ks)[36] = reinterpret_cast<unsigned(*)[36]>(sraw + 128 * 36);
    float (*epi)[136]  = reinterpret_cast<float(*)[136]>(sraw);  // 34.8 KB

    const int tid = threadIdx.x;
    const int warp = tid >> 5;
    const int lane = tid & 31;
    const int wm = (warp >> 2) * 64;
    const int wn = (warp & 3) * 32;
    const int lr = lane >> 2;
    const int lc = lane & 3;

    float c[4][4][4] = {};

    for (int k0 = 0; k0 < DK; k0 += 32) {
        {
            const int r = tid >> 1;
            const int cb = (tid & 1) * 16;
            const float* src = &g_Q[(size_t)(b * SS + bm + r) * DM + h * DK + k0 + cb];
            #pragma unroll
            for (int i = 0; i < 4; i++) {
                float4 v = *reinterpret_cast<const float4*>(src + i * 4);
                Qs[r][cb + i*4 + 0] = f2tf(v.x);
                Qs[r][cb + i*4 + 1] = f2tf(v.y);
                Qs[r][cb + i*4 + 2] = f2tf(v.z);
                Qs[r][cb + i*4 + 3] = f2tf(v.w);
            }
            const float* ksrc = &g_Kp[(size_t)(b * SS + bn + r) * DK + k0 + cb];
            #pragma unroll
            for (int i = 0; i < 4; i++) {
                float4 v = *reinterpret_cast<const float4*>(ksrc + i * 4);
                Ks[r][cb + i*4 + 0] = f2tf(v.x);
                Ks[r][cb + i*4 + 1] = f2tf(v.y);
                Ks[r][cb + i*4 + 2] = f2tf(v.z);
                Ks[r][cb + i*4 + 3] = f2tf(v.w);
            }
        }
        __syncthreads();

        #pragma unroll
        for (int ks = 0; ks < 4; ks++) {
            const int kb = ks * 8;
            unsigned a[4][4], bf[4][2];
            #pragma unroll
            for (int mt = 0; mt < 4; mt++) {
                int r0 = wm + mt * 16 + lr;
                a[mt][0] = Qs[r0    ][kb + lc];
                a[mt][1] = Qs[r0 + 8][kb + lc];
                a[mt][2] = Qs[r0    ][kb + 4 + lc];
                a[mt][3] = Qs[r0 + 8][kb + 4 + lc];
            }
            #pragma unroll
            for (int nt = 0; nt < 4; nt++) {
                int n0 = wn + nt * 8 + lr;
                bf[nt][0] = Ks[n0][kb + lc];
                bf[nt][1] = Ks[n0][kb + 4 + lc];
            }
            #pragma unroll
            for (int mt = 0; mt < 4; mt++)
                #pragma unroll
                for (int nt = 0; nt < 4; nt++)
                    mma_tf32(c[mt][nt], a[mt], bf[nt]);
        }
        __syncthreads();   // also protects the smem union before the epilogue
    }

    // Coalesced epilogue: two 64-row chunks (warps 0-3 own rows 0-63,
    // warps 4-7 own rows 64-127 — wm picks the owner).
    const float scale = 0.125f;
    #pragma unroll
    for (int chunk = 0; chunk < 2; chunk++) {
        if ((warp >> 2) == chunk) {
            #pragma unroll
            for (int mt = 0; mt < 4; mt++) {
                #pragma unroll
                for (int half = 0; half < 2; half++) {
                    int row = mt * 16 + lr + half * 8;   // 0..63 (local)
                    #pragma unroll
                    for (int nt = 0; nt < 4; nt++) {
                        int col = wn + nt * 8 + lc * 2;
                        float2 v;
                        v.x = c[mt][nt][half * 2 + 0] * scale;
                        v.y = c[mt][nt][half * 2 + 1] * scale;
                        *reinterpret_cast<float2*>(&epi[row][col]) = v;
                    }
                }
            }
        }
        __syncthreads();

        // All threads: coalesced float4 stores of 64x128 floats.
        #pragma unroll
        for (int j = 0; j < 8; j++) {
            int flat = tid * 4 + j * 1024;
            int row = flat >> 7;       // 0..63
            int col = flat & 127;
            float4 v = *reinterpret_cast<const float4*>(&epi[row][col]);
            size_t m = (size_t)bh * SS + bm + chunk * 64 + row;
            *reinterpret_cast<float4*>(&attn[m * SS + bn + col]) = v;
        }
        __syncthreads();
    }
}

// ---------------------------------------------------------------------------
// Row softmax (S=2048). One block per row, in-place. (R15 version)
// ---------------------------------------------------------------------------
__global__ void softmax_kernel(float* __restrict__ attn) {
    const size_t row = blockIdx.x;
    float4* p4 = reinterpret_cast<float4*>(attn + row * SS);
    const int tid = threadIdx.x;
    const int lane = tid & 31;
    const int warp = tid >> 5;

    __shared__ float red[8];

    float4 a = p4[tid];
    float4 b = p4[tid + 256];

    float m = fmaxf(fmaxf(fmaxf(a.x, a.y), fmaxf(a.z, a.w)),
                    fmaxf(fmaxf(b.x, b.y), fmaxf(b.z, b.w)));
    #pragma unroll
    for (int d = 16; d > 0; d >>= 1)
        m = fmaxf(m, __shfl_xor_sync(0xffffffffu, m, d));
    if (lane == 0) red[warp] = m;
    __syncthreads();
    float M = red[0];
    #pragma unroll
    for (int w = 1; w < 8; w++) M = fmaxf(M, red[w]);

    a.x = __expf(a.x - M); a.y = __expf(a.y - M);
    a.z = __expf(a.z - M); a.w = __expf(a.w - M);
    b.x = __expf(b.x - M); b.y = __expf(b.y - M);
    b.z = __expf(b.z - M); b.w = __expf(b.w - M);
    float s = (a.x + a.y + a.z + a.w) + (b.x + b.y + b.z + b.w);
    #pragma unroll
    for (int d = 16; d > 0; d >>= 1)
        s += __shfl_xor_sync(0xffffffffu, s, d);
    __syncthreads();
    if (lane == 0) red[warp] = s;
    __syncthreads();
    float S = red[0];
    #pragma unroll
    for (int w = 1; w < 8; w++) S += red[w];
    const float inv = 1.f / S;

    a.x *= inv; a.y *= inv; a.z *= inv; a.w *= inv;
    b.x *= inv; b.y *= inv; b.z *= inv; b.w *= inv;
    p4[tid] = a;
    p4[tid + 256] = b;
}

// ---------------------------------------------------------------------------
// heads = attn @ V via TF32 MMA with 2-stage cp.async pipeline (R15 winner).
// ---------------------------------------------------------------------------
__global__ void av_tc_kernel(const float* __restrict__ attn) {
    const int bh = blockIdx.y;
    const int b = bh >> 4;
    const int h = bh & 15;
    const int bm = blockIdx.x * 128;

    const float* A = attn + (size_t)bh * SS * SS;

    __shared__ unsigned As_[2][128][36];
    __shared__ unsigned Vs[32][68];

    const int tid = threadIdx.x;
    const int warp = tid >> 5;
    const int lane = tid & 31;
    const int wm = (warp >> 1) * 32;
    const int wn = (warp & 1) * 32;
    const int lr = lane >> 2;
    const int lc = lane & 3;

    const int NIT = SS / 32;   // 64

    {
        #pragma unroll
        for (int j = 0; j < 4; j++) {
            int idx = tid + j * 256;
            int r = idx >> 3, cc = idx & 7;
            cp_async16(&As_[0][r][cc * 4], &A[(size_t)(bm + r) * SS + cc * 4]);
        }
        cp_commit();
    }

    float c[2][4][4] = {};

    for (int i = 0; i < NIT; i++) {
        const int s = i & 1;

        if (i + 1 < NIT) {
            const int k0n = (i + 1) * 32;
            #pragma unroll
            for (int j = 0; j < 4; j++) {
                int idx = tid + j * 256;
                int r = idx >> 3, cc = idx & 7;
                cp_async16(&As_[s ^ 1][r][cc * 4],
                           &A[(size_t)(bm + r) * SS + k0n + cc * 4]);
            }
            cp_commit();
        }

        {
            const int k0 = i * 32;
            const int r = tid >> 3;
            const int cb = (tid & 7) * 8;
            const float* src = &g_Vp[(size_t)(b * SS + k0 + r) * DK + cb];
            #pragma unroll
            for (int ii = 0; ii < 2; ii++) {
                float4 v = *reinterpret_cast<const float4*>(src + ii * 4);
                Vs[r][cb + ii*4 + 0] = f2tf(v.x);
                Vs[r][cb + ii*4 + 1] = f2tf(v.y);
                Vs[r][cb + ii*4 + 2] = f2tf(v.z);
                Vs[r][cb + ii*4 + 3] = f2tf(v.w);
            }
        }

        if (i + 1 < NIT) {
            asm volatile("cp.async.wait_group 1;");
        } else {
            asm volatile("cp.async.wait_group 0;");
        }
        __syncthreads();

        #pragma unroll
        for (int ks = 0; ks < 4; ks++) {
            const int kb = ks * 8;
            unsigned a[2][4], bf[4][2];
            #pragma unroll
            for (int mt = 0; mt < 2; mt++) {
                int r0 = wm + mt * 16 + lr;
                a[mt][0] = u2tf(As_[s][r0    ][kb + lc]);
                a[mt][1] = u2tf(As_[s][r0 + 8][kb + lc]);
                a[mt][2] = u2tf(As_[s][r0    ][kb + 4 + lc]);
                a[mt][3] = u2tf(As_[s][r0 + 8][kb + 4 + lc]);
            }
            #pragma unroll
            for (int nt = 0; nt < 4; nt++) {
                int n0 = wn + nt * 8 + lr;
                bf[nt][0] = Vs[kb + lc    ][n0];
                bf[nt][1] = Vs[kb + 4 + lc][n0];
            }
            #pragma unroll
            for (int mt = 0; mt < 2; mt++)
                #pragma unroll
                for (int nt = 0; nt < 4; nt++)
                    mma_tf32(c[mt][nt], a[mt], bf[nt]);
        }
        __syncthreads();
    }

    // Scrambled-reshape store (matches reference heads.reshape(B,S,D_MODEL)).
    #pragma unroll
    for (int mt = 0; mt < 2; mt++) {
        #pragma unroll
        for (int half = 0; half < 2; half++) {
            int sq = bm + wm + mt * 16 + lr + half * 8;
            size_t row = (size_t)b * SS + h * 128 + (sq >> 4);
            int cpart = (sq & 15) * 64;
            #pragma unroll
            for (int nt = 0; nt < 4; nt++) {
                int d = wn + nt * 8 + lc * 2;
                float2 v;
                v.x = c[mt][nt][half * 2 + 0];
                v.y = c[mt][nt][half * 2 + 1];
                *reinterpret_cast<float2*>(&g_AO[row * DM + cpart + d]) = v;
            }
        }
    }
}

// ---------------------------------------------------------------------------
// Launch
// ---------------------------------------------------------------------------
extern "C" void kernel_launch(void* const* d_in, const int* in_sizes, int n_in,
                              void* d_out, int out_size) {
    const float* query = (const float*)d_in[0];
    const float* key_  = (const float*)d_in[1];
    const float* value = (const float*)d_in[2];
    const float* w_q   = (const float*)d_in[3];
    const float* b_q   = (const float*)d_in[4];
    const float* w_k   = (const float*)d_in[5];
    const float* b_k   = (const float*)d_in[6];
    const float* w_v   = (const float*)d_in[7];
    const float* b_v   = (const float*)d_in[8];
    const float* w_o   = (const float*)d_in[9];
    const float* b_o   = (const float*)d_in[10];

    float *Qp, *Kp, *Vp, *AO, *attn_scr;
    cudaGetSymbolAddress((void**)&Qp, g_Q);
    cudaGetSymbolAddress((void**)&Kp, g_Kp);
    cudaGetSymbolAddress((void**)&Vp, g_Vp);
    cudaGetSymbolAddress((void**)&AO, g_AO);
    cudaGetSymbolAddress((void**)&attn_scr, g_attn_scratch);

    float* out = (float*)d_out;
    const size_t OUT_ELEMS  = (size_t)BB * SS * DM;
    const size_t ATTN_ELEMS = (size_t)BB * NH * SS * SS;

    float* attn = ((size_t)out_size >= OUT_ELEMS + ATTN_ELEMS)
                      ? (out + OUT_ELEMS)
                      : attn_scr;

    const int M = BB * SS;   // 4096
    dim3 thr(256);

    // Projections
    gemm_bias_bf16x3_kernel<<<dim3(M / 128, DM / 128), thr>>>(query, w_q, b_q, Qp, M, DM, DM);
    gemm_bias_kv_kernel<<<dim3(M / 64, 2), thr>>>(key_, value, w_k, b_k, w_v, b_v, Kp, Vp);

    // Scores + softmax
    scores_tc_kernel<<<dim3(SS / 128, SS / 128, BHX), thr>>>(attn);
    softmax_kernel<<<dim3((unsigned)((size_t)BHX * SS)), thr>>>(attn);

    // attn @ V (double-buffered cp.async, reference reshape layout)
    av_tc_kernel<<<dim3(SS / 128, BHX), thr>>>(attn);

    // Output projection
    gemm_bias_bf16x3_kernel<<<dim3(M / 128, DM / 128), thr>>>(AO, w_o, b_o, out, M, DM, DM);
}

// round 17
// speedup vs baseline: 1.3996x; 1.3996x over previous
#include <cuda_runtime.h>
#include <cuda_bf16.h>
#include <math.h>
#include <stddef.h>

// Problem constants
#define BB 2
#define SS 2048
#define DM 1024
#define NH 16
#define DK 64
#define BHX (BB * NH)   // 32

// ---------------------------------------------------------------------------
// Scratch (device globals; no allocation allowed)
// ---------------------------------------------------------------------------
__device__ float g_Q [(size_t)BB * SS * DM];
__device__ float g_Kp[(size_t)BB * SS * DK];
__device__ float g_Vp[(size_t)BB * SS * DK];
__device__ float g_AO[(size_t)BB * SS * DM];
__device__ float g_attn_scratch[(size_t)BB * NH * SS * SS];

// ---------------------------------------------------------------------------
// TF32 helpers (fragment layouts validated in R7)
// ---------------------------------------------------------------------------
__device__ __forceinline__ unsigned f2tf(float x) {
    unsigned r;
    asm("cvt.rna.tf32.f32 %0, %1;" : "=r"(r) : "f"(x));
    return r;
}

__device__ __forceinline__ unsigned u2tf(unsigned ub) {
    return f2tf(__uint_as_float(ub));
}

__device__ __forceinline__ void mma_tf32(float c[4], const unsigned a[4], const unsigned b[2]) {
    asm volatile(
        "mma.sync.aligned.m16n8k8.row.col.f32.tf32.tf32.f32 "
        "{%0,%1,%2,%3}, {%4,%5,%6,%7}, {%8,%9}, {%0,%1,%2,%3};"
        : "+f"(c[0]), "+f"(c[1]), "+f"(c[2]), "+f"(c[3])
        : "r"(a[0]), "r"(a[1]), "r"(a[2]), "r"(a[3]), "r"(b[0]), "r"(b[1]));
}

// ---------------------------------------------------------------------------
// cp.async helpers
// ---------------------------------------------------------------------------
__device__ __forceinline__ void cp_async16(const void* smem_ptr, const void* gmem_ptr) {
    unsigned sa = (unsigned)__cvta_generic_to_shared(smem_ptr);
    asm volatile("cp.async.cg.shared.global [%0], [%1], 16;" :: "r"(sa), "l"(gmem_ptr));
}
__device__ __forceinline__ void cp_commit() {
    asm volatile("cp.async.commit_group;");
}

// ---------------------------------------------------------------------------
// BF16 helpers (m16n8k16; validated in R13)
// ---------------------------------------------------------------------------
__device__ __forceinline__ void mma_bf16(float c[4], const unsigned a[4], const unsigned b[2]) {
    asm volatile(
        "mma.sync.aligned.m16n8k16.row.col.f32.bf16.bf16.f32 "
        "{%0,%1,%2,%3}, {%4,%5,%6,%7}, {%8,%9}, {%0,%1,%2,%3};"
        : "+f"(c[0]), "+f"(c[1]), "+f"(c[2]), "+f"(c[3])
        : "r"(a[0]), "r"(a[1]), "r"(a[2]), "r"(a[3]), "r"(b[0]), "r"(b[1]));
}

__device__ __forceinline__ void split2_bf16(float x, float y, unsigned& h, unsigned& l) {
    __nv_bfloat16 hx = __float2bfloat16_rn(x);
    __nv_bfloat16 hy = __float2bfloat16_rn(y);
    __nv_bfloat16 lx = __float2bfloat16_rn(x - __bfloat162float(hx));
    __nv_bfloat16 ly = __float2bfloat16_rn(y - __bfloat162float(hy));
    h = (unsigned)__bfloat16_as_ushort(hx) | ((unsigned)__bfloat16_as_ushort(hy) << 16);
    l = (unsigned)__bfloat16_as_ushort(lx) | ((unsigned)__bfloat16_as_ushort(ly) << 16);
}

// ---------------------------------------------------------------------------
// Fused K/V projection: grid.y = 0 -> K, 1 -> V.  SIMT fp32, N=64.
// One launch, 128 blocks (vs two serial 64-block launches).
// ---------------------------------------------------------------------------
__global__ void gemm_bias_kv_kernel(const float* __restrict__ Kin,
                                    const float* __restrict__ Vin,
                                    const float* __restrict__ w_k,
                                    const float* __restrict__ b_k,
                                    const float* __restrict__ w_v,
                                    const float* __restrict__ b_v,
                                    float* __restrict__ Kout,
                                    float* __restrict__ Vout) {
    const int which = blockIdx.y;
    const float* A    = which ? Vin  : Kin;
    const float* W    = which ? w_v  : w_k;
    const float* bias = which ? b_v  : b_k;
    float*       C    = which ? Vout : Kout;

    const int M = BB * SS;      // 4096
    const int K = DM;           // 1024
    const int N = DK;           // 64

    __shared__ float As[16][68];
    __shared__ float Ws[16][64];

    const int tid = threadIdx.x;
    const int tx = tid & 15;
    const int ty = tid >> 4;
    const int bm = blockIdx.x * 64;

    float acc[4][4] = {};

    for (int k0 = 0; k0 < K; k0 += 16) {
        #pragma unroll
        for (int i = tid; i < 64 * 16; i += 256) {
            int m = i >> 4, k = i & 15;
            As[k][m] = A[(size_t)(bm + m) * K + k0 + k];
        }
        #pragma unroll
        for (int i = tid; i < 16 * 64; i += 256) {
            int k = i >> 6, n = i & 63;
            Ws[k][n] = W[(size_t)(k0 + k) * N + n];
        }
        __syncthreads();

        #pragma unroll
        for (int k = 0; k < 16; k++) {
            float4 avv = *reinterpret_cast<const float4*>(&As[k][ty * 4]);
            float a[4] = {avv.x, avv.y, avv.z, avv.w};
            float4 bv = *reinterpret_cast<const float4*>(&Ws[k][tx * 4]);
            float b[4] = {bv.x, bv.y, bv.z, bv.w};
            #pragma unroll
            for (int i = 0; i < 4; i++)
                #pragma unroll
                for (int j = 0; j < 4; j++)
                    acc[i][j] = fmaf(a[i], b[j], acc[i][j]);
        }
        __syncthreads();
    }

    #pragma unroll
    for (int i = 0; i < 4; i++) {
        int m = bm + ty * 4 + i;
        #pragma unroll
        for (int j = 0; j < 4; j++) {
            int n = tx * 4 + j;
            C[(size_t)m * N + n] = acc[i][j] + bias[n];
        }
    }
}

// ---------------------------------------------------------------------------
// BF16-split ("bf16x3") tensor-core GEMM with bias (validated R13)
// ---------------------------------------------------------------------------
__global__ void gemm_bias_bf16x3_kernel(const float* __restrict__ A,
                                        const float* __restrict__ W,
                                        const float* __restrict__ bias,
                                        float* __restrict__ C,
                                        int M, int K, int N) {
    __shared__ unsigned Ah[128][13];
    __shared__ unsigned Al[128][13];
    __shared__ unsigned Wh[128][13];
    __shared__ unsigned Wl[128][13];

    const int tid = threadIdx.x;
    const int warp = tid >> 5;
    const int lane = tid & 31;
    const int wm = (warp >> 2) * 64;
    const int wn = (warp & 3) * 32;
    const int lr = lane >> 2;
    const int lc = lane & 3;
    const int bm = blockIdx.x * 128;
    const int bn = blockIdx.y * 128;

    float c[4][4][4] = {};

    for (int k0 = 0; k0 < K; k0 += 16) {
        {
            const int r = tid >> 1;
            const int cb = (tid & 1) * 8;
            const int pb = (tid & 1) * 4;
            const float* src = &A[(size_t)(bm + r) * K + k0 + cb];
            float4 v0 = *reinterpret_cast<const float4*>(src);
            float4 v1 = *reinterpret_cast<const float4*>(src + 4);
            unsigned h, l;
            split2_bf16(v0.x, v0.y, h, l); Ah[r][pb + 0] = h; Al[r][pb + 0] = l;
            split2_bf16(v0.z, v0.w, h, l); Ah[r][pb + 1] = h; Al[r][pb + 1] = l;
            split2_bf16(v1.x, v1.y, h, l); Ah[r][pb + 2] = h; Al[r][pb + 2] = l;
            split2_bf16(v1.z, v1.w, h, l); Ah[r][pb + 3] = h; Al[r][pb + 3] = l;
        }
        {
            const int kk2 = warp * 2;
            const int nb = lane * 4;
            const float* src0 = &W[(size_t)(k0 + kk2    ) * N + bn + nb];
            const float* src1 = &W[(size_t)(k0 + kk2 + 1) * N + bn + nb];
            float4 r0 = *reinterpret_cast<const float4*>(src0);
            float4 r1 = *reinterpret_cast<const float4*>(src1);
            unsigned h, l;
            split2_bf16(r0.x, r1.x, h, l); Wh[nb + 0][warp] = h; Wl[nb + 0][warp] = l;
            split2_bf16(r0.y, r1.y, h, l); Wh[nb + 1][warp] = h; Wl[nb + 1][warp] = l;
            split2_bf16(r0.z, r1.z, h, l); Wh[nb + 2][warp] = h; Wl[nb + 2][warp] = l;
            split2_bf16(r0.w, r1.w, h, l); Wh[nb + 3][warp] = h; Wl[nb + 3][warp] = l;
        }
        __syncthreads();

        unsigned ah[4][4], al[4][4], bh[4][2], bl[4][2];
        #pragma unroll
        for (int mt = 0; mt < 4; mt++) {
            int r0 = wm + mt * 16 + lr;
            ah[mt][0] = Ah[r0    ][lc];
            ah[mt][1] = Ah[r0 + 8][lc];
            ah[mt][2] = Ah[r0    ][lc + 4];
            ah[mt][3] = Ah[r0 + 8][lc + 4];
            al[mt][0] = Al[r0    ][lc];
            al[mt][1] = Al[r0 + 8][lc];
            al[mt][2] = Al[r0    ][lc + 4];
            al[mt][3] = Al[r0 + 8][lc + 4];
        }
        #pragma unroll
        for (int nt = 0; nt < 4; nt++) {
            int n0 = wn + nt * 8 + lr;
            bh[nt][0] = Wh[n0][lc];
            bh[nt][1] = Wh[n0][lc + 4];
            bl[nt][0] = Wl[n0][lc];
            bl[nt][1] = Wl[n0][lc + 4];
        }
        #pragma unroll
        for (int mt = 0; mt < 4; mt++)
            #pragma unroll
            for (int nt = 0; nt < 4; nt++) {
                mma_bf16(c[mt][nt], al[mt], bh[nt]);
                mma_bf16(c[mt][nt], ah[mt], bl[nt]);
                mma_bf16(c[mt][nt], ah[mt], bh[nt]);
            }
        __syncthreads();
    }

    #pragma unroll
    for (int mt = 0; mt < 4; mt++) {
        #pragma unroll
        for (int half = 0; half < 2; half++) {
            int m = bm + wm + mt * 16 + lr + half * 8;
            #pragma unroll
            for (int nt = 0; nt < 4; nt++) {
                int n = bn + wn + nt * 8 + lc * 2;
                float2 bv = *reinterpret_cast<const float2*>(&bias[n]);
                float2 v;
                v.x = c[mt][nt][half * 2 + 0] + bv.x;
                v.y = c[mt][nt][half * 2 + 1] + bv.y;
                *reinterpret_cast<float2*>(&C[(size_t)m * N + n]) = v;
            }
        }
    }
}

// ---------------------------------------------------------------------------
// Scores via TF32 MMA (R13/R15 winner version — direct-store epilogue)
// ---------------------------------------------------------------------------
__global__ void scores_tc_kernel(float* __restrict__ attn) {
    const int bh = blockIdx.z;
    const int b = bh >> 4;
    const int h = bh & 15;
    const int bm = blockIdx.x * 128;
    const int bn = blockIdx.y * 128;

    __shared__ unsigned Qs[128][36];
    __shared__ unsigned Ks[128][36];

    const int tid = threadIdx.x;
    const int warp = tid >> 5;
    const int lane = tid & 31;
    const int wm = (warp >> 2) * 64;
    const int wn = (warp & 3) * 32;
    const int lr = lane >> 2;
    const int lc = lane & 3;

    float c[4][4][4] = {};

    for (int k0 = 0; k0 < DK; k0 += 32) {
        {
            const int r = tid >> 1;
            const int cb = (tid & 1) * 16;
            const float* src = &g_Q[(size_t)(b * SS + bm + r) * DM + h * DK + k0 + cb];
            #pragma unroll
            for (int i = 0; i < 4; i++) {
                float4 v = *reinterpret_cast<const float4*>(src + i * 4);
                Qs[r][cb + i*4 + 0] = f2tf(v.x);
                Qs[r][cb + i*4 + 1] = f2tf(v.y);
                Qs[r][cb + i*4 + 2] = f2tf(v.z);
                Qs[r][cb + i*4 + 3] = f2tf(v.w);
            }
            const float* ksrc = &g_Kp[(size_t)(b * SS + bn + r) * DK + k0 + cb];
            #pragma unroll
            for (int i = 0; i < 4; i++) {
                float4 v = *reinterpret_cast<const float4*>(ksrc + i * 4);
                Ks[r][cb + i*4 + 0] = f2tf(v.x);
                Ks[r][cb + i*4 + 1] = f2tf(v.y);
                Ks[r][cb + i*4 + 2] = f2tf(v.z);
                Ks[r][cb + i*4 + 3] = f2tf(v.w);
            }
        }
        __syncthreads();

        #pragma unroll
        for (int ks = 0; ks < 4; ks++) {
            const int kb = ks * 8;
            unsigned a[4][4], bf[4][2];
            #pragma unroll
            for (int mt = 0; mt < 4; mt++) {
                int r0 = wm + mt * 16 + lr;
                a[mt][0] = Qs[r0    ][kb + lc];
                a[mt][1] = Qs[r0 + 8][kb + lc];
                a[mt][2] = Qs[r0    ][kb + 4 + lc];
                a[mt][3] = Qs[r0 + 8][kb + 4 + lc];
            }
            #pragma unroll
            for (int nt = 0; nt < 4; nt++) {
                int n0 = wn + nt * 8 + lr;
                bf[nt][0] = Ks[n0][kb + lc];
                bf[nt][1] = Ks[n0][kb + 4 + lc];
            }
            #pragma unroll
            for (int mt = 0; mt < 4; mt++)
                #pragma unroll
                for (int nt = 0; nt < 4; nt++)
                    mma_tf32(c[mt][nt], a[mt], bf[nt]);
        }
        __syncthreads();
    }

    const float scale = 0.125f;
    #pragma unroll
    for (int mt = 0; mt < 4; mt++) {
        #pragma unroll
        for (int half = 0; half < 2; half++) {
            int m = bm + wm + mt * 16 + lr + half * 8;
            size_t rowbase = ((size_t)bh * SS + m) * SS;
            #pragma unroll
            for (int nt = 0; nt < 4; nt++) {
                int n = bn + wn + nt * 8 + lc * 2;
                float2 v;
                v.x = c[mt][nt][half * 2 + 0] * scale;
                v.y = c[mt][nt][half * 2 + 1] * scale;
                *reinterpret_cast<float2*>(&attn[rowbase + n]) = v;
            }
        }
    }
}

// ---------------------------------------------------------------------------
// Row softmax (S=2048). One block per row, in-place. (R15 version)
// ---------------------------------------------------------------------------
__global__ void softmax_kernel(float* __restrict__ attn) {
    const size_t row = blockIdx.x;
    float4* p4 = reinterpret_cast<float4*>(attn + row * SS);
    const int tid = threadIdx.x;
    const int lane = tid & 31;
    const int warp = tid >> 5;

    __shared__ float red[8];

    float4 a = p4[tid];
    float4 b = p4[tid + 256];

    float m = fmaxf(fmaxf(fmaxf(a.x, a.y), fmaxf(a.z, a.w)),
                    fmaxf(fmaxf(b.x, b.y), fmaxf(b.z, b.w)));
    #pragma unroll
    for (int d = 16; d > 0; d >>= 1)
        m = fmaxf(m, __shfl_xor_sync(0xffffffffu, m, d));
    if (lane == 0) red[warp] = m;
    __syncthreads();
    float M = red[0];
    #pragma unroll
    for (int w = 1; w < 8; w++) M = fmaxf(M, red[w]);

    a.x = __expf(a.x - M); a.y = __expf(a.y - M);
    a.z = __expf(a.z - M); a.w = __expf(a.w - M);
    b.x = __expf(b.x - M); b.y = __expf(b.y - M);
    b.z = __expf(b.z - M); b.w = __expf(b.w - M);
    float s = (a.x + a.y + a.z + a.w) + (b.x + b.y + b.z + b.w);
    #pragma unroll
    for (int d = 16; d > 0; d >>= 1)
        s += __shfl_xor_sync(0xffffffffu, s, d);
    __syncthreads();
    if (lane == 0) red[warp] = s;
    __syncthreads();
    float S = red[0];
    #pragma unroll
    for (int w = 1; w < 8; w++) S += red[w];
    const float inv = 1.f / S;

    a.x *= inv; a.y *= inv; a.z *= inv; a.w *= inv;
    b.x *= inv; b.y *= inv; b.z *= inv; b.w *= inv;
    p4[tid] = a;
    p4[tid + 256] = b;
}

// ---------------------------------------------------------------------------
// heads = attn @ V via TF32 MMA with 2-stage cp.async pipeline (R15 winner).
// ---------------------------------------------------------------------------
__global__ void av_tc_kernel(const float* __restrict__ attn) {
    const int bh = blockIdx.y;
    const int b = bh >> 4;
    const int h = bh & 15;
    const int bm = blockIdx.x * 128;

    const float* A = attn + (size_t)bh * SS * SS;

    __shared__ unsigned As_[2][128][36];
    __shared__ unsigned Vs[32][68];

    const int tid = threadIdx.x;
    const int warp = tid >> 5;
    const int lane = tid & 31;
    const int wm = (warp >> 1) * 32;
    const int wn = (warp & 1) * 32;
    const int lr = lane >> 2;
    const int lc = lane & 3;

    const int NIT = SS / 32;   // 64

    {
        #pragma unroll
        for (int j = 0; j < 4; j++) {
            int idx = tid + j * 256;
            int r = idx >> 3, cc = idx & 7;
            cp_async16(&As_[0][r][cc * 4], &A[(size_t)(bm + r) * SS + cc * 4]);
        }
        cp_commit();
    }

    float c[2][4][4] = {};

    for (int i = 0; i < NIT; i++) {
        const int s = i & 1;

        if (i + 1 < NIT) {
            const int k0n = (i + 1) * 32;
            #pragma unroll
            for (int j = 0; j < 4; j++) {
                int idx = tid + j * 256;
                int r = idx >> 3, cc = idx & 7;
                cp_async16(&As_[s ^ 1][r][cc * 4],
                           &A[(size_t)(bm + r) * SS + k0n + cc * 4]);
            }
            cp_commit();
        }

        {
            const int k0 = i * 32;
            const int r = tid >> 3;
            const int cb = (tid & 7) * 8;
            const float* src = &g_Vp[(size_t)(b * SS + k0 + r) * DK + cb];
            #pragma unroll
            for (int ii = 0; ii < 2; ii++) {
                float4 v = *reinterpret_cast<const float4*>(src + ii * 4);
                Vs[r][cb + ii*4 + 0] = f2tf(v.x);
                Vs[r][cb + ii*4 + 1] = f2tf(v.y);
                Vs[r][cb + ii*4 + 2] = f2tf(v.z);
                Vs[r][cb + ii*4 + 3] = f2tf(v.w);
            }
        }

        if (i + 1 < NIT) {
            asm volatile("cp.async.wait_group 1;");
        } else {
            asm volatile("cp.async.wait_group 0;");
        }
        __syncthreads();

        #pragma unroll
        for (int ks = 0; ks < 4; ks++) {
            const int kb = ks * 8;
            unsigned a[2][4], bf[4][2];
            #pragma unroll
            for (int mt = 0; mt < 2; mt++) {
                int r0 = wm + mt * 16 + lr;
                a[mt][0] = u2tf(As_[s][r0    ][kb + lc]);
                a[mt][1] = u2tf(As_[s][r0 + 8][kb + lc]);
                a[mt][2] = u2tf(As_[s][r0    ][kb + 4 + lc]);
                a[mt][3] = u2tf(As_[s][r0 + 8][kb + 4 + lc]);
            }
            #pragma unroll
            for (int nt = 0; nt < 4; nt++) {
                int n0 = wn + nt * 8 + lr;
                bf[nt][0] = Vs[kb + lc    ][n0];
                bf[nt][1] = Vs[kb + 4 + lc][n0];
            }
            #pragma unroll
            for (int mt = 0; mt < 2; mt++)
                #pragma unroll
                for (int nt = 0; nt < 4; nt++)
                    mma_tf32(c[mt][nt], a[mt], bf[nt]);
        }
        __syncthreads();
    }

    // Scrambled-reshape store (matches reference heads.reshape(B,S,D_MODEL)).
    #pragma unroll
    for (int mt = 0; mt < 2; mt++) {
        #pragma unroll
        for (int half = 0; half < 2; half++) {
            int sq = bm + wm + mt * 16 + lr + half * 8;
            size_t row = (size_t)b * SS + h * 128 + (sq >> 4);
            int cpart = (sq & 15) * 64;
            #pragma unroll
            for (int nt = 0; nt < 4; nt++) {
                int d = wn + nt * 8 + lc * 2;
                float2 v;
                v.x = c[mt][nt][half * 2 + 0];
                v.y = c[mt][nt][half * 2 + 1];
                *reinterpret_cast<float2*>(&g_AO[row * DM + cpart + d]) = v;
            }
        }
    }
}

// ---------------------------------------------------------------------------
// Launch
// ---------------------------------------------------------------------------
extern "C" void kernel_launch(void* const* d_in, const int* in_sizes, int n_in,
                              void* d_out, int out_size) {
    const float* query = (const float*)d_in[0];
    const float* key_  = (const float*)d_in[1];
    const float* value = (const float*)d_in[2];
    const float* w_q   = (const float*)d_in[3];
    const float* b_q   = (const float*)d_in[4];
    const float* w_k   = (const float*)d_in[5];
    const float* b_k   = (const float*)d_in[6];
    const float* w_v   = (const float*)d_in[7];
    const float* b_v   = (const float*)d_in[8];
    const float* w_o   = (const float*)d_in[9];
    const float* b_o   = (const float*)d_in[10];

    float *Qp, *Kp, *Vp, *AO, *attn_scr;
    cudaGetSymbolAddress((void**)&Qp, g_Q);
    cudaGetSymbolAddress((void**)&Kp, g_Kp);
    cudaGetSymbolAddress((void**)&Vp, g_Vp);
    cudaGetSymbolAddress((void**)&AO, g_AO);
    cudaGetSymbolAddress((void**)&attn_scr, g_attn_scratch);

    float* out = (float*)d_out;
    const size_t OUT_ELEMS  = (size_t)BB * SS * DM;
    const size_t ATTN_ELEMS = (size_t)BB * NH * SS * SS;

    float* attn = ((size_t)out_size >= OUT_ELEMS + ATTN_ELEMS)
                      ? (out + OUT_ELEMS)
                      : attn_scr;

    const int M = BB * SS;   // 4096
    dim3 thr(256);

    // Projections
    gemm_bias_bf16x3_kernel<<<dim3(M / 128, DM / 128), thr>>>(query, w_q, b_q, Qp, M, DM, DM);
    gemm_bias_kv_kernel<<<dim3(M / 64, 2), thr>>>(key_, value, w_k, b_k, w_v, b_v, Kp, Vp);

    // Scores + softmax
    scores_tc_kernel<<<dim3(SS / 128, SS / 128, BHX), thr>>>(attn);
    softmax_kernel<<<dim3((unsigned)((size_t)BHX * SS)), thr>>>(attn);

    // attn @ V (double-buffered cp.async, reference reshape layout)
    av_tc_kernel<<<dim3(SS / 128, BHX), thr>>>(attn);

    // Output projection
    gemm_bias_bf16x3_kernel<<<dim3(M / 128, DM / 128), thr>>>(AO, w_o, b_o, out, M, DM, DM);
}